// round 13
// baseline (speedup 1.0000x reference)
#include <cuda_runtime.h>
#include <cuda_fp16.h>
#include <math.h>
#include <stdint.h>

// Problem constants
#define Bn   4
#define Cc   256
#define Hh   64
#define Ww   64
#define Pp   256
#define NK   9
#define PADc 6
#define DILc 6
#define Hp   76
#define Wp   76
#define Mpix (Bn*Hh*Ww)     // 16384
#define Kdim (Cc*NK)        // 2304
#define NIT  (Kdim/32)      // 72

// ---------------- scratch ----------------
__device__ float  g_offmask[Bn * 27 * Hh * Ww];                  // [b][ch0..26][h][w]
__device__ float  g_xt[(size_t)Mpix * Cc];                       // xT fp32 [m][c]
__device__ __half g_xh[(size_t)Mpix * Cc];                       // xT hi [m][c]
__device__ __half g_xl[(size_t)Mpix * Cc];                       // xT lo
__device__ __half g_Wch[72 * 32 * 32];                           // conv W hi [it][o][c32]
__device__ __half g_colh[(size_t)Mpix * Kdim];                   // A hi [m][k], k = kk*256+c
__device__ __half g_coll[(size_t)Mpix * Kdim];                   // A lo [m][k]
__device__ __half g_Bh[(size_t)NIT * Pp * 32];                   // B hi [kc][o][32]
__device__ float  g_y[(size_t)Mpix * Pp];                        // y[m][o]
__device__ float  g_psum[128 * Pp];
__device__ float  g_psum2[128 * Pp];
__device__ float  g_scale[Pp];
__device__ float  g_shift[Pp];

#define SW128(off) ((off) ^ (((off) >> 3) & 0x70))

// ---------------- ptx helpers ----------------
__device__ __forceinline__ uint32_t smem_u32(const void* p) {
    uint32_t a;
    asm("{ .reg .u64 t; cvta.to.shared.u64 t, %1; cvt.u32.u64 %0, t; }" : "=r"(a) : "l"(p));
    return a;
}
__device__ __forceinline__ void cpasync16(uint32_t s, const void* g) {
    asm volatile("cp.async.cg.shared.global [%0], [%1], 16;" :: "r"(s), "l"(g));
}
__device__ __forceinline__ void cpasync16z(uint32_t s, const void* g, uint32_t srcsz) {
    asm volatile("cp.async.cg.shared.global [%0], [%1], 16, %2;" :: "r"(s), "l"(g), "r"(srcsz));
}
__device__ __forceinline__ void cp_commit() {
    asm volatile("cp.async.commit_group;" ::: "memory");
}
template <int N> __device__ __forceinline__ void cp_wait() {
    asm volatile("cp.async.wait_group %0;" :: "n"(N) : "memory");
}
__device__ __forceinline__ void ldsm4(uint32_t* r, uint32_t a) {
    asm volatile("ldmatrix.sync.aligned.m8n8.x4.shared.b16 {%0,%1,%2,%3}, [%4];"
                 : "=r"(r[0]), "=r"(r[1]), "=r"(r[2]), "=r"(r[3]) : "r"(a));
}
__device__ __forceinline__ void mma16816(float* c, const uint32_t* a, const uint32_t* b) {
    asm volatile("mma.sync.aligned.m16n8k16.row.col.f32.f16.f16.f32 "
                 "{%0,%1,%2,%3}, {%4,%5,%6,%7}, {%8,%9}, {%0,%1,%2,%3};"
                 : "+f"(c[0]), "+f"(c[1]), "+f"(c[2]), "+f"(c[3])
                 : "r"(a[0]), "r"(a[1]), "r"(a[2]), "r"(a[3]), "r"(b[0]), "r"(b[1]));
}

// ---------------- kernel 1: x transpose + fp32 copy + fp16 split ----------------
__global__ __launch_bounds__(256) void k_xsplit(const float* __restrict__ x)
{
    __shared__ float t[32][33];
    int hw0 = blockIdx.x * 32;
    int c0  = blockIdx.y * 32;
    int b   = blockIdx.z;
    int tx = threadIdx.x, ty = threadIdx.y;

    #pragma unroll
    for (int p = 0; p < 4; p++)
        t[ty + 8 * p][tx] = x[(size_t)(b * 256 + c0 + ty + 8 * p) * 4096 + hw0 + tx];
    __syncthreads();
    #pragma unroll
    for (int p = 0; p < 4; p++) {
        float v = t[tx][ty + 8 * p];
        __half hi = __float2half_rn(v);
        float lo = v - __half2float(hi);
        size_t idx = (size_t)(b * 4096 + hw0 + ty + 8 * p) * 256 + c0 + tx;
        g_xt[idx] = v;
        g_xh[idx] = hi;
        g_xl[idx] = __float2half_rn(lo);
    }
}

// ---------------- kernel 2: conv weight pack (hi only) ----------------
__global__ __launch_bounds__(256) void k_wcpack(
    const float* __restrict__ w_p, const float* __restrict__ w_m)
{
    int i = blockIdx.x * 256 + threadIdx.x;     // 0..73727
    int it = i >> 10, o = (i >> 5) & 31, ci = i & 31;
    int j = it >> 3, cc = it & 7;
    int c = cc * 32 + ci;
    float v = 0.f;
    if (o < 18)      v = w_p[(size_t)o * Kdim + c * 9 + j];
    else if (o < 27) v = w_m[(size_t)(o - 18) * Kdim + c * 9 + j];
    g_Wch[i] = __float2half_rn(v);
}

// ---------------- kernel 3: offset+mask conv as HMMA GEMM (2-pass) ----------------
#define CSTAGE 18432
__global__ __launch_bounds__(256, 2) void k_convmma(
    const float* __restrict__ b_p, const float* __restrict__ b_m)
{
    __shared__ char csm[2][CSTAGE];
    __shared__ float sbias[32];
    uint32_t sb0 = smem_u32(&csm[0][0]);
    int tid = threadIdx.x;
    int lane = tid & 31, wid = tid >> 5;
    int m0 = blockIdx.x * 128;

    if (tid < 32) sbias[tid] = (tid < 18) ? b_p[tid] : (tid < 27 ? b_m[tid - 18] : 0.f);

    int q = lane >> 3, r = lane & 7;
    int arow = wid * 16 + r + (q & 1) * 8;
    int acix = q >> 1;
    uint32_t aso_base = (uint32_t)(arow * 64);
    int arsw = (arow >> 1) & 3;

    int bn[2], bsw[2];
    int cq = q & 1;
    #pragma unroll
    for (int g = 0; g < 2; g++) {
        int n = g * 16 + ((q >> 1) & 1) * 8 + r;
        bn[g] = n * 64;
        bsw[g] = (n >> 1) & 3;
    }

    float acc[4][4];
    #pragma unroll
    for (int fn = 0; fn < 4; fn++)
        #pragma unroll
        for (int i = 0; i < 4; i++) acc[fn][i] = 0.f;

    auto issue = [&](int it, int buf) {
        uint32_t sst = sb0 + buf * CSTAGE;
        int j = it >> 3, cc = it & 7;
        int dh = j / 3 - 1, dw = j % 3 - 1;
        int delta = dh * 64 + dw;
        int c0 = cc * 32;
        #pragma unroll
        for (int p = 0; p < 4; p++) {
            int id = tid + p * 256;
            int row = id >> 3, sub = id & 7;
            int half = sub >> 2, ci = sub & 3;
            int h = ((m0 + row) >> 6) & 63, w = row & 63;
            bool valid = ((unsigned)(h + dh) < 64u) && ((unsigned)(w + dw) < 64u);
            const __half* src = (half ? g_xl : g_xh);
            const __half* gp = valid ? (src + (size_t)(m0 + row + delta) * 256 + c0 + ci * 8)
                                     : src;
            uint32_t dst = sst + half * 8192 + row * 64 + ((ci ^ ((row >> 1) & 3)) << 4);
            cpasync16z(dst, gp, valid ? 16u : 0u);
        }
        if (tid < 128) {
            int o = tid >> 2, ci = tid & 3;
            const __half* gp = g_Wch + ((size_t)it * 32 + o) * 32 + ci * 8;
            uint32_t dst = sst + 16384 + o * 64 + ((ci ^ ((o >> 1) & 3)) << 4);
            cpasync16(dst, gp);
        }
    };

    issue(0, 0);
    cp_commit();

    for (int it = 0; it < 72; it++) {
        if (it + 1 < 72) {
            issue(it + 1, (it + 1) & 1);
            cp_commit();
            cp_wait<1>();
        } else {
            cp_wait<0>();
        }
        __syncthreads();

        uint32_t abase = sb0 + (it & 1) * CSTAGE;
        uint32_t bbase = abase + 16384;

        #pragma unroll
        for (int ks = 0; ks < 2; ks++) {
            uint32_t ah[4], al[4], bq[2][4];
            {
                int ci = ks * 2 + acix;
                uint32_t so = aso_base + ((ci ^ arsw) << 4);
                ldsm4(ah, abase + so);
                ldsm4(al, abase + 8192 + so);
            }
            #pragma unroll
            for (int g = 0; g < 2; g++)
                ldsm4(bq[g], bbase + bn[g] + (((ks * 2 + cq) ^ bsw[g]) << 4));
            #pragma unroll
            for (int g = 0; g < 2; g++)
                #pragma unroll
                for (int h = 0; h < 2; h++) {
                    mma16816(acc[g * 2 + h], ah, &bq[g][h * 2]);
                    mma16816(acc[g * 2 + h], al, &bq[g][h * 2]);
                }
        }
        __syncthreads();
    }

    int mbase = m0 + wid * 16 + (lane >> 2);
    #pragma unroll
    for (int fn = 0; fn < 4; fn++) {
        #pragma unroll
        for (int hf = 0; hf < 2; hf++) {
            int m = mbase + hf * 8;
            int b = m >> 12, hw = m & 4095;
            #pragma unroll
            for (int e = 0; e < 2; e++) {
                int o = fn * 8 + (lane & 3) * 2 + e;
                if (o < 27)
                    g_offmask[(size_t)(b * 27 + o) * 4096 + hw] = acc[fn][hf * 2 + e] + sbias[o];
            }
        }
    }
}

// ---------------- kernel 4: coalesced deformable sampling (fp32 taps) ----------------
__global__ __launch_bounds__(256) void k_sample2()
{
    int wid = threadIdx.x >> 5, lane = threadIdx.x & 31;
    int id = blockIdx.x * 8 + wid;            // 0..147455
    int m = id / 9, kk = id - m * 9;
    int b = m >> 12, hw = m & 4095;
    int h = hw >> 6, w = hw & 63;

    float offx = g_offmask[(size_t)(b * 27 + kk) * 4096 + hw];
    float offy = g_offmask[(size_t)(b * 27 + 9 + kk) * 4096 + hw];
    float mlog = g_offmask[(size_t)(b * 27 + 18 + kk) * 4096 + hw];
    float mask = 1.f / (1.f + expf(-mlog));

    int knh = kk / 3, knw = kk % 3;
    float px = (float)(h + 1) + (float)((knh - 1) * DILc) + offx;
    float py = (float)(w + 1) + (float)((knw - 1) * DILc) + offy;

    float flx = floorf(px), fly = floorf(py);
    float qltx = fminf(fmaxf(flx,       0.f), (float)(Hp - 1));
    float qlty = fminf(fmaxf(fly,       0.f), (float)(Wp - 1));
    float qrbx = fminf(fmaxf(flx + 1.f, 0.f), (float)(Hp - 1));
    float qrby = fminf(fmaxf(fly + 1.f, 0.f), (float)(Wp - 1));
    float pxc  = fminf(fmaxf(px, 0.f), (float)(Hp - 1));
    float pyc  = fminf(fmaxf(py, 0.f), (float)(Wp - 1));

    float glt = (1.f + (qltx - pxc)) * (1.f + (qlty - pyc)) * mask;
    float grb = (1.f - (qrbx - pxc)) * (1.f - (qrby - pyc)) * mask;
    float glb = (1.f + (qltx - pxc)) * (1.f - (qrby - pyc)) * mask;
    float grt = (1.f - (qrbx - pxc)) * (1.f + (qlty - pyc)) * mask;

    int ltx = (int)qltx - PADc, lty = (int)qlty - PADc;
    int rbx = (int)qrbx - PADc, rby = (int)qrby - PADc;
    bool vltx = (unsigned)ltx < (unsigned)Hh, vlty = (unsigned)lty < (unsigned)Ww;
    bool vrbx = (unsigned)rbx < (unsigned)Hh, vrby = (unsigned)rby < (unsigned)Ww;

    bool bLT = vltx && vlty, bRB = vrbx && vrby;
    bool bLB = vltx && vrby, bRT = vrbx && vlty;

    float  wgt[4];
    size_t tap[4];
    int mb = b * 4096;
    wgt[0] = bLT ? glt : 0.f;  tap[0] = (size_t)(mb + (bLT ? (ltx * Ww + lty) : 0)) * 256;
    wgt[1] = bRB ? grb : 0.f;  tap[1] = (size_t)(mb + (bRB ? (rbx * Ww + rby) : 0)) * 256;
    wgt[2] = bLB ? glb : 0.f;  tap[2] = (size_t)(mb + (bLB ? (ltx * Ww + rby) : 0)) * 256;
    wgt[3] = bRT ? grt : 0.f;  tap[3] = (size_t)(mb + (bRT ? (rbx * Ww + lty) : 0)) * 256;

    size_t obase = (size_t)m * Kdim + kk * 256;

    #pragma unroll
    for (int step = 0; step < 2; step++) {
        int c = (step * 32 + lane) * 4;       // 4 channels per lane
        float4 v = make_float4(0.f, 0.f, 0.f, 0.f);
        #pragma unroll
        for (int t = 0; t < 4; t++) {
            float4 xv = *(const float4*)(g_xt + tap[t] + c);
            v.x = fmaf(wgt[t], xv.x, v.x);
            v.y = fmaf(wgt[t], xv.y, v.y);
            v.z = fmaf(wgt[t], xv.z, v.z);
            v.w = fmaf(wgt[t], xv.w, v.w);
        }
        __half h0 = __float2half_rn(v.x), h1 = __float2half_rn(v.y);
        __half h2 = __float2half_rn(v.z), h3 = __float2half_rn(v.w);
        __half l0 = __float2half_rn(v.x - __half2float(h0));
        __half l1 = __float2half_rn(v.y - __half2float(h1));
        __half l2 = __float2half_rn(v.z - __half2float(h2));
        __half l3 = __float2half_rn(v.w - __half2float(h3));
        uint2 oh, ol;
        *(__half2*)&oh.x = __halves2half2(h0, h1);
        *(__half2*)&oh.y = __halves2half2(h2, h3);
        *(__half2*)&ol.x = __halves2half2(l0, l1);
        *(__half2*)&ol.y = __halves2half2(l2, l3);
        *(uint2*)&g_colh[obase + c] = oh;
        *(uint2*)&g_coll[obase + c] = ol;
    }
}

// ---------------- kernel 5: main weight pack (hi only, kk-major k order) ----------------
__global__ __launch_bounds__(256) void k_wpack(const float* __restrict__ w)
{
    int i = blockIdx.x * 256 + threadIdx.x;
    if (i < Pp * Kdim) {
        int o = i / Kdim, kold = i % Kdim;    // kold = c*9 + kk
        int c = kold / 9, kk = kold - c * 9;
        int kn = kk * 256 + c;
        size_t idx = (size_t)(kn >> 5) * (Pp * 32) + o * 32 + (kn & 31);
        g_Bh[idx] = __float2half_rn(w[i]);
    }
}

// ---------------- kernel 6: main HMMA GEMM 128m x 256n, 2-pass, 3-stage pipeline ----------------
// stage 32 KB: Ah[0,8K) (128m x 64B rows), Al[8K,16K), Bh[16K,32K) (256o x 64B rows)
#define STAGE 32768
#define GEMM_SMEM (3 * STAGE)

__device__ __forceinline__ void issue_tile(int kc, uint32_t sst, int tid, int m0)
{
    int k0 = kc * 32;
    #pragma unroll
    for (int p = 0; p < 2; p++) {
        int id = tid + p * 256;               // 0..511
        int row = id >> 2, ci = id & 3;
        size_t gofs = ((size_t)(m0 + row) * Kdim + k0) * 2 + ci * 16;
        uint32_t so = (uint32_t)(row * 64 + ((ci ^ ((row >> 1) & 3)) << 4));
        cpasync16(sst + so, (const char*)g_colh + gofs);
        cpasync16(sst + 8192 + so, (const char*)g_coll + gofs);
    }
    #pragma unroll
    for (int p = 0; p < 4; p++) {
        int id = tid + p * 256;               // 0..1023
        int o = id >> 2, cc = id & 3;
        uint32_t so = (uint32_t)(o * 64 + ((cc ^ ((o >> 1) & 3)) << 4));
        const __half* gh = g_Bh + (size_t)kc * (Pp * 32) + o * 32 + cc * 8;
        cpasync16(sst + 16384 + so, gh);
    }
}

__global__ __launch_bounds__(256) void k_gemm_mma()
{
    extern __shared__ char smem[];
    uint32_t sb = smem_u32(smem);
    int tid = threadIdx.x;
    int lane = tid & 31, wid = tid >> 5;
    int wm = wid & 1, wn = wid >> 1;          // warp tile: 64m x 64n
    int m0 = blockIdx.x * 128;

    int q = lane >> 3, r = lane & 7;
    int acix = q >> 1;
    uint32_t aoff[4];
    int asw[4];
    #pragma unroll
    for (int fm = 0; fm < 4; fm++) {
        int row = wm * 64 + fm * 16 + (q & 1) * 8 + r;
        aoff[fm] = (uint32_t)(row * 64);
        asw[fm] = (row >> 1) & 3;
    }
    int bno[4], bsw[4];
    int cq = q & 1;
    #pragma unroll
    for (int g = 0; g < 4; g++) {
        int n = wn * 64 + g * 16 + ((q >> 1) & 1) * 8 + r;
        bno[g] = n * 64;
        bsw[g] = (n >> 1) & 3;
    }

    float acc[4][8][4];
    #pragma unroll
    for (int fm = 0; fm < 4; fm++)
        #pragma unroll
        for (int fn = 0; fn < 8; fn++)
            #pragma unroll
            for (int i = 0; i < 4; i++) acc[fm][fn][i] = 0.f;

    issue_tile(0, sb, tid, m0);
    cp_commit();
    issue_tile(1, sb + STAGE, tid, m0);
    cp_commit();

    int buf = 0;
    for (int it = 0; it < NIT; it++) {
        if (it + 2 < NIT) {
            int nb = buf + 2; if (nb >= 3) nb -= 3;
            issue_tile(it + 2, sb + nb * STAGE, tid, m0);
        }
        cp_commit();
        cp_wait<2>();
        __syncthreads();

        uint32_t abase = sb + buf * STAGE;
        uint32_t bbase = abase + 16384;

        #pragma unroll
        for (int ks = 0; ks < 2; ks++) {
            uint32_t ah[4][4], al[4][4], bq[4][4];
            #pragma unroll
            for (int fm = 0; fm < 4; fm++) {
                int ci = ks * 2 + acix;
                uint32_t so = aoff[fm] + ((ci ^ asw[fm]) << 4);
                ldsm4(ah[fm], abase + so);
                ldsm4(al[fm], abase + 8192 + so);
            }
            #pragma unroll
            for (int g = 0; g < 4; g++)
                ldsm4(bq[g], bbase + bno[g] + (((ks * 2 + cq) ^ bsw[g]) << 4));
            #pragma unroll
            for (int g = 0; g < 4; g++)
                #pragma unroll
                for (int h = 0; h < 2; h++)
                    #pragma unroll
                    for (int fm = 0; fm < 4; fm++) {
                        mma16816(acc[fm][g * 2 + h], ah[fm], &bq[g][h * 2]);
                        mma16816(acc[fm][g * 2 + h], al[fm], &bq[g][h * 2]);
                    }
        }
        __syncthreads();
        if (++buf == 3) buf = 0;
    }

    int mrow = m0 + wm * 64 + (lane >> 2);
    int ocol = wn * 64 + (lane & 3) * 2;
    #pragma unroll
    for (int fm = 0; fm < 4; fm++) {
        int m = mrow + fm * 16;
        #pragma unroll
        for (int fn = 0; fn < 8; fn++) {
            int o = ocol + fn * 8;
            *(float2*)&g_y[(size_t)m * Pp + o]       = make_float2(acc[fm][fn][0], acc[fm][fn][1]);
            *(float2*)&g_y[(size_t)(m + 8) * Pp + o] = make_float2(acc[fm][fn][2], acc[fm][fn][3]);
        }
    }
}

// ---------------- kernel 7: BN partial stats ----------------
__global__ __launch_bounds__(256) void k_bnstats()
{
    int bb = blockIdx.x, t = threadIdx.x;
    float s = 0.f, s2 = 0.f;
    const float* yr = g_y + (size_t)bb * 128 * Pp + t;
    for (int i = 0; i < 128; i++) {
        float v = yr[(size_t)i * Pp];
        s += v;
        s2 = fmaf(v, v, s2);
    }
    g_psum[bb * Pp + t] = s;
    g_psum2[bb * Pp + t] = s2;
}

// ---------------- kernel 8: BN finalize ----------------
__global__ __launch_bounds__(256) void k_bnfin(
    const float* __restrict__ gamma, const float* __restrict__ beta)
{
    int o = threadIdx.x;
    float s = 0.f, s2 = 0.f;
    for (int b = 0; b < 128; b++) {
        s += g_psum[b * Pp + o];
        s2 += g_psum2[b * Pp + o];
    }
    float mean = s * (1.f / (float)Mpix);
    float var = s2 * (1.f / (float)Mpix) - mean * mean;
    float sc = gamma[o] * rsqrtf(var + 1e-5f);
    g_scale[o] = sc;
    g_shift[o] = beta[o] - mean * sc;
}

// ---------------- kernel 9: BN apply + ReLU ----------------
__global__ __launch_bounds__(256) void k_bnapply(float* __restrict__ out)
{
    __shared__ float st[256][36];
    __shared__ float sc[256], sh[256];
    int t = threadIdx.x;
    int m0 = blockIdx.x * 32;
    sc[t] = g_scale[t];
    sh[t] = g_shift[t];
    __syncthreads();

    #pragma unroll
    for (int p = 0; p < 8; p++) {
        int idx = t + p * 256;
        int mi = idx >> 6, oc4 = idx & 63;
        float4 v = *(const float4*)&g_y[(size_t)(m0 + mi) * Pp + oc4 * 4];
        int o = oc4 * 4;
        st[o + 0][mi] = fmaxf(fmaf(v.x, sc[o + 0], sh[o + 0]), 0.f);
        st[o + 1][mi] = fmaxf(fmaf(v.y, sc[o + 1], sh[o + 1]), 0.f);
        st[o + 2][mi] = fmaxf(fmaf(v.z, sc[o + 2], sh[o + 2]), 0.f);
        st[o + 3][mi] = fmaxf(fmaf(v.w, sc[o + 3], sh[o + 3]), 0.f);
    }
    __syncthreads();

    int b = m0 >> 12;
    int hw0 = m0 & 4095;
    #pragma unroll
    for (int p = 0; p < 8; p++) {
        int idx = t + p * 256;
        int o = idx >> 3, mq = idx & 7;
        float4 v = *(const float4*)&st[o][mq * 4];
        *(float4*)&out[(size_t)(b * 256 + o) * 4096 + hw0 + mq * 4] = v;
    }
}

// ---------------- launch ----------------
extern "C" void kernel_launch(void* const* d_in, const int* in_sizes, int n_in,
                              void* d_out, int out_size)
{
    const float* x     = (const float*)d_in[0];
    const float* w_p   = (const float*)d_in[1];
    const float* b_p   = (const float*)d_in[2];
    const float* w_m   = (const float*)d_in[3];
    const float* b_m   = (const float*)d_in[4];
    const float* w     = (const float*)d_in[5];
    const float* gamma = (const float*)d_in[6];
    const float* beta  = (const float*)d_in[7];
    float* out = (float*)d_out;

    cudaFuncSetAttribute(k_gemm_mma, cudaFuncAttributeMaxDynamicSharedMemorySize, GEMM_SMEM);

    k_xsplit<<<dim3(128, 8, Bn), dim3(32, 8)>>>(x);
    k_wcpack<<<288, 256>>>(w_p, w_m);
    k_convmma<<<Mpix / 128, 256>>>(b_p, b_m);
    k_sample2<<<Mpix * 9 / 8, 256>>>();
    k_wpack<<<(Pp * Kdim + 255) / 256, 256>>>(w);
    k_gemm_mma<<<Mpix / 128, 256, GEMM_SMEM>>>();
    k_bnstats<<<128, 256>>>();
    k_bnfin<<<1, 256>>>(gamma, beta);
    k_bnapply<<<Mpix / 32, 256>>>(out);
}

// round 14
// speedup vs baseline: 1.5214x; 1.5214x over previous
#include <cuda_runtime.h>
#include <cuda_fp16.h>
#include <math.h>
#include <stdint.h>

// Problem constants
#define Bn   4
#define Cc   256
#define Hh   64
#define Ww   64
#define Pp   256
#define NK   9
#define PADc 6
#define DILc 6
#define Hp   76
#define Wp   76
#define Mpix (Bn*Hh*Ww)     // 16384
#define Kdim (Cc*NK)        // 2304
#define NIT  (Kdim/32)      // 72
#define PW   66             // padded width/height for xT
#define PROW (PW*PW)        // 4356 padded pixels per image

// ---------------- scratch ----------------
__device__ float  g_offmask[Bn * 27 * Hh * Ww];                  // [b][ch0..26][h][w]
__device__ __half g_xph[(size_t)Bn * PROW * Cc];                 // padded xT hi [b][h'][w'][c] (pad rows stay 0)
__device__ __half g_xpl[(size_t)Bn * PROW * Cc];                 // padded xT lo
__device__ __half g_Wch[8 * 9 * 32 * 32];                        // conv W hi [cc][j][o][c32]
__device__ __half g_colh[(size_t)Mpix * Kdim];                   // A hi [m][k], k = kk*256+c
__device__ __half g_coll[(size_t)Mpix * Kdim];                   // A lo [m][k]
__device__ __half g_Bh[(size_t)NIT * Pp * 32];                   // B hi [kc][o][32]
__device__ float  g_y[(size_t)Mpix * Pp];                        // y[m][o]
__device__ float  g_psum[128 * Pp];
__device__ float  g_psum2[128 * Pp];
__device__ float  g_scale[Pp];
__device__ float  g_shift[Pp];

#define SW128(off) ((off) ^ (((off) >> 3) & 0x70))

// ---------------- ptx helpers ----------------
__device__ __forceinline__ uint32_t smem_u32(const void* p) {
    uint32_t a;
    asm("{ .reg .u64 t; cvta.to.shared.u64 t, %1; cvt.u32.u64 %0, t; }" : "=r"(a) : "l"(p));
    return a;
}
__device__ __forceinline__ void cpasync16(uint32_t s, const void* g) {
    asm volatile("cp.async.cg.shared.global [%0], [%1], 16;" :: "r"(s), "l"(g));
}
__device__ __forceinline__ void cp_commit() {
    asm volatile("cp.async.commit_group;" ::: "memory");
}
template <int N> __device__ __forceinline__ void cp_wait() {
    asm volatile("cp.async.wait_group %0;" :: "n"(N) : "memory");
}
__device__ __forceinline__ void ldsm4(uint32_t* r, uint32_t a) {
    asm volatile("ldmatrix.sync.aligned.m8n8.x4.shared.b16 {%0,%1,%2,%3}, [%4];"
                 : "=r"(r[0]), "=r"(r[1]), "=r"(r[2]), "=r"(r[3]) : "r"(a));
}
__device__ __forceinline__ void mma16816(float* c, const uint32_t* a, const uint32_t* b) {
    asm volatile("mma.sync.aligned.m16n8k16.row.col.f32.f16.f16.f32 "
                 "{%0,%1,%2,%3}, {%4,%5,%6,%7}, {%8,%9}, {%0,%1,%2,%3};"
                 : "+f"(c[0]), "+f"(c[1]), "+f"(c[2]), "+f"(c[3])
                 : "r"(a[0]), "r"(a[1]), "r"(a[2]), "r"(a[3]), "r"(b[0]), "r"(b[1]));
}

// ---------------- kernel 1: x transpose + fp16 split into padded layout ----------------
__global__ __launch_bounds__(256) void k_xsplit(const float* __restrict__ x)
{
    __shared__ float t[32][33];
    int hw0 = blockIdx.x * 32;
    int c0  = blockIdx.y * 32;
    int b   = blockIdx.z;
    int tx = threadIdx.x, ty = threadIdx.y;

    #pragma unroll
    for (int p = 0; p < 4; p++)
        t[ty + 8 * p][tx] = x[(size_t)(b * 256 + c0 + ty + 8 * p) * 4096 + hw0 + tx];
    __syncthreads();
    #pragma unroll
    for (int p = 0; p < 4; p++) {
        float v = t[tx][ty + 8 * p];
        __half hi = __float2half_rn(v);
        float lo = v - __half2float(hi);
        int hw = hw0 + ty + 8 * p;
        int h = hw >> 6, w = hw & 63;
        size_t prow = (size_t)b * PROW + (h + 1) * PW + (w + 1);
        size_t idx = prow * 256 + c0 + tx;
        g_xph[idx] = hi;
        g_xpl[idx] = __float2half_rn(lo);
    }
}

// ---------------- kernel 2: conv weight pack [cc][j][o][c32] (hi only) ----------------
__global__ __launch_bounds__(256) void k_wcpack(
    const float* __restrict__ w_p, const float* __restrict__ w_m)
{
    int i = blockIdx.x * 256 + threadIdx.x;     // 0..73727
    int ci = i & 31, o = (i >> 5) & 31;
    int rest = i >> 10;                          // 0..71
    int j = rest % 9, cc = rest / 9;
    int c = cc * 32 + ci;
    float v = 0.f;
    if (o < 18)      v = w_p[(size_t)o * Kdim + c * 9 + j];
    else if (o < 27) v = w_m[(size_t)(o - 18) * Kdim + c * 9 + j];
    g_Wch[i] = __float2half_rn(v);
}

// ---------------- kernel 3: offset+mask conv as HMMA GEMM, halo tiles over padded xT ----------------
// per CTA: 128 out pixels (2 h-rows), 8 c-chunks; per chunk load 264-row halo (hi+lo) once,
// run all 9 taps from it via ldsm row offsets. Zero padding = conv pad semantics.
#define CA_BYTES 16896                       // 264 rows * 64B
#define CASTAGE  (2 * CA_BYTES)              // hi + lo
#define CB_BYTES 18432                       // 9j * 32o * 64B
#define CONV_SMEM (2 * CASTAGE + 2 * CB_BYTES)   // 104448
__global__ __launch_bounds__(256) void k_convmma(
    const float* __restrict__ b_p, const float* __restrict__ b_m)
{
    extern __shared__ char dsm[];
    __shared__ float sbias[32];
    uint32_t sa  = smem_u32(dsm);
    uint32_t sbb = sa + 2 * CASTAGE;
    int tid = threadIdx.x;
    int lane = tid & 31, wid = tid >> 5;
    int m0 = blockIdx.x * 128;
    int b = m0 >> 12, h0 = (m0 & 4095) >> 6;
    size_t pbase = (size_t)b * PROW + h0 * PW;   // first halo row

    if (tid < 32) sbias[tid] = (tid < 18) ? b_p[tid] : (tid < 27 ? b_m[tid - 18] : 0.f);

    int q = lane >> 3, r = lane & 7;
    int ml = wid * 16 + (q & 1) * 8 + r;         // this thread's A-frag out-pixel
    int r0 = (ml >> 6) * PW + (ml & 63);         // halo-local base row (before tap offset)
    int acix = q >> 1;
    int cq = q & 1;
    int bnrow[2];
    #pragma unroll
    for (int g = 0; g < 2; g++)
        bnrow[g] = g * 16 + ((q >> 1) & 1) * 8 + r;

    float acc[4][4];
    #pragma unroll
    for (int fn = 0; fn < 4; fn++)
        #pragma unroll
        for (int i = 0; i < 4; i++) acc[fn][i] = 0.f;

    auto issue = [&](int cc, int buf) {
        uint32_t sA = sa + buf * CASTAGE;
        uint32_t sB = sbb + buf * CB_BYTES;
        #pragma unroll
        for (int p = 0; p < 9; p++) {
            int id = tid + p * 256;
            if (id < 2112) {
                int half = id >= 1056;
                int e = id - half * 1056;
                int row = e >> 2, ci = e & 3;
                const __half* src = (half ? g_xpl : g_xph) + (pbase + row) * 256 + cc * 32 + ci * 8;
                cpasync16(sA + half * CA_BYTES + row * 64 + ((ci ^ ((row >> 1) & 3)) << 4), src);
            }
        }
        #pragma unroll
        for (int p = 0; p < 5; p++) {
            int id = tid + p * 256;
            if (id < 1152) {
                int row = id >> 2, ci = id & 3;    // row = j*32 + o
                cpasync16(sB + row * 64 + ((ci ^ ((row >> 1) & 3)) << 4),
                          g_Wch + (size_t)cc * 9216 + row * 32 + ci * 8);
            }
        }
    };

    issue(0, 0);
    cp_commit();

    for (int cc = 0; cc < 8; cc++) {
        if (cc + 1 < 8) {
            issue(cc + 1, (cc + 1) & 1);
            cp_commit();
            cp_wait<1>();
        } else {
            cp_wait<0>();
        }
        __syncthreads();

        uint32_t abase = sa + (cc & 1) * CASTAGE;
        uint32_t bbase = sbb + (cc & 1) * CB_BYTES;

        #pragma unroll
        for (int j = 0; j < 9; j++) {
            int joff = (j / 3) * PW + (j % 3);
            int arow = r0 + joff;
            uint32_t arbase = (uint32_t)(arow * 64);
            int asel = (arow >> 1) & 3;
            #pragma unroll
            for (int ks = 0; ks < 2; ks++) {
                uint32_t ah[4], al[4], bq[2][4];
                int ci = ks * 2 + acix;
                uint32_t soa = arbase + ((ci ^ asel) << 4);
                ldsm4(ah, abase + soa);
                ldsm4(al, abase + CA_BYTES + soa);
                #pragma unroll
                for (int g = 0; g < 2; g++) {
                    int brow = j * 32 + bnrow[g];
                    ldsm4(bq[g], bbase + brow * 64 + (((ks * 2 + cq) ^ ((brow >> 1) & 3)) << 4));
                }
                #pragma unroll
                for (int g = 0; g < 2; g++)
                    #pragma unroll
                    for (int h = 0; h < 2; h++) {
                        mma16816(acc[g * 2 + h], ah, &bq[g][h * 2]);
                        mma16816(acc[g * 2 + h], al, &bq[g][h * 2]);
                    }
            }
        }
        __syncthreads();
    }

    int mbase = m0 + wid * 16 + (lane >> 2);
    #pragma unroll
    for (int fn = 0; fn < 4; fn++) {
        #pragma unroll
        for (int hf = 0; hf < 2; hf++) {
            int m = mbase + hf * 8;
            int bb = m >> 12, hw = m & 4095;
            #pragma unroll
            for (int e = 0; e < 2; e++) {
                int o = fn * 8 + (lane & 3) * 2 + e;
                if (o < 27)
                    g_offmask[(size_t)(bb * 27 + o) * 4096 + hw] = acc[fn][hf * 2 + e] + sbias[o];
            }
        }
    }
}

// ---------------- kernel 4: coalesced deformable sampling (hi/lo taps, padded xT) ----------------
__global__ __launch_bounds__(256) void k_sample2()
{
    int wid = threadIdx.x >> 5, lane = threadIdx.x & 31;
    int id = blockIdx.x * 8 + wid;            // 0..147455
    int m = id / 9, kk = id - m * 9;
    int b = m >> 12, hw = m & 4095;
    int h = hw >> 6, w = hw & 63;

    float offx = g_offmask[(size_t)(b * 27 + kk) * 4096 + hw];
    float offy = g_offmask[(size_t)(b * 27 + 9 + kk) * 4096 + hw];
    float mlog = g_offmask[(size_t)(b * 27 + 18 + kk) * 4096 + hw];
    float mask = 1.f / (1.f + expf(-mlog));

    int knh = kk / 3, knw = kk % 3;
    float px = (float)(h + 1) + (float)((knh - 1) * DILc) + offx;
    float py = (float)(w + 1) + (float)((knw - 1) * DILc) + offy;

    float flx = floorf(px), fly = floorf(py);
    float qltx = fminf(fmaxf(flx,       0.f), (float)(Hp - 1));
    float qlty = fminf(fmaxf(fly,       0.f), (float)(Wp - 1));
    float qrbx = fminf(fmaxf(flx + 1.f, 0.f), (float)(Hp - 1));
    float qrby = fminf(fmaxf(fly + 1.f, 0.f), (float)(Wp - 1));
    float pxc  = fminf(fmaxf(px, 0.f), (float)(Hp - 1));
    float pyc  = fminf(fmaxf(py, 0.f), (float)(Wp - 1));

    float glt = (1.f + (qltx - pxc)) * (1.f + (qlty - pyc)) * mask;
    float grb = (1.f - (qrbx - pxc)) * (1.f - (qrby - pyc)) * mask;
    float glb = (1.f + (qltx - pxc)) * (1.f - (qrby - pyc)) * mask;
    float grt = (1.f - (qrbx - pxc)) * (1.f + (qlty - pyc)) * mask;

    int ltx = (int)qltx - PADc, lty = (int)qlty - PADc;
    int rbx = (int)qrbx - PADc, rby = (int)qrby - PADc;
    bool vltx = (unsigned)ltx < (unsigned)Hh, vlty = (unsigned)lty < (unsigned)Ww;
    bool vrbx = (unsigned)rbx < (unsigned)Hh, vrby = (unsigned)rby < (unsigned)Ww;

    bool bLT = vltx && vlty, bRB = vrbx && vrby;
    bool bLB = vltx && vrby, bRT = vrbx && vlty;

    float  wgt[4];
    size_t tap[4];
    size_t pb = (size_t)b * PROW;
    wgt[0] = bLT ? glt : 0.f;  tap[0] = (pb + (bLT ? ((ltx + 1) * PW + lty + 1) : 0)) * 256;
    wgt[1] = bRB ? grb : 0.f;  tap[1] = (pb + (bRB ? ((rbx + 1) * PW + rby + 1) : 0)) * 256;
    wgt[2] = bLB ? glb : 0.f;  tap[2] = (pb + (bLB ? ((ltx + 1) * PW + rby + 1) : 0)) * 256;
    wgt[3] = bRT ? grt : 0.f;  tap[3] = (pb + (bRT ? ((rbx + 1) * PW + lty + 1) : 0)) * 256;

    size_t obase = (size_t)m * Kdim + kk * 256;

    #pragma unroll
    for (int step = 0; step < 2; step++) {
        int c = (step * 32 + lane) * 4;       // 4 channels per lane
        float2 v01 = make_float2(0.f, 0.f);
        float2 v23 = make_float2(0.f, 0.f);
        #pragma unroll
        for (int t = 0; t < 4; t++) {
            uint2 hh = *(const uint2*)(g_xph + tap[t] + c);
            uint2 ll = *(const uint2*)(g_xpl + tap[t] + c);
            float2 h01 = __half22float2(*(__half2*)&hh.x);
            float2 h23 = __half22float2(*(__half2*)&hh.y);
            float2 l01 = __half22float2(*(__half2*)&ll.x);
            float2 l23 = __half22float2(*(__half2*)&ll.y);
            v01.x = fmaf(wgt[t], h01.x + l01.x, v01.x);
            v01.y = fmaf(wgt[t], h01.y + l01.y, v01.y);
            v23.x = fmaf(wgt[t], h23.x + l23.x, v23.x);
            v23.y = fmaf(wgt[t], h23.y + l23.y, v23.y);
        }
        __half h0 = __float2half_rn(v01.x), h1 = __float2half_rn(v01.y);
        __half h2 = __float2half_rn(v23.x), h3 = __float2half_rn(v23.y);
        __half l0 = __float2half_rn(v01.x - __half2float(h0));
        __half l1 = __float2half_rn(v01.y - __half2float(h1));
        __half l2 = __float2half_rn(v23.x - __half2float(h2));
        __half l3 = __float2half_rn(v23.y - __half2float(h3));
        uint2 oh, ol;
        *(__half2*)&oh.x = __halves2half2(h0, h1);
        *(__half2*)&oh.y = __halves2half2(h2, h3);
        *(__half2*)&ol.x = __halves2half2(l0, l1);
        *(__half2*)&ol.y = __halves2half2(l2, l3);
        *(uint2*)&g_colh[obase + c] = oh;
        *(uint2*)&g_coll[obase + c] = ol;
    }
}

// ---------------- kernel 5: main weight pack (hi only, kk-major k order) ----------------
__global__ __launch_bounds__(256) void k_wpack(const float* __restrict__ w)
{
    int i = blockIdx.x * 256 + threadIdx.x;
    if (i < Pp * Kdim) {
        int o = i / Kdim, kold = i % Kdim;    // kold = c*9 + kk
        int c = kold / 9, kk = kold - c * 9;
        int kn = kk * 256 + c;
        size_t idx = (size_t)(kn >> 5) * (Pp * 32) + o * 32 + (kn & 31);
        g_Bh[idx] = __float2half_rn(w[i]);
    }
}

// ---------------- kernel 6: main HMMA GEMM 128x128 tiles, 2-pass, A m-major (R11 config) ----------------
#define STAGE 24576
#define GEMM_SMEM (2 * STAGE)

__device__ __forceinline__ void issue_tile(int kc, uint32_t sst, int tid, int m0, int n0)
{
    int k0 = kc * 32;
    #pragma unroll
    for (int p = 0; p < 2; p++) {
        int id = tid + p * 256;               // 0..511
        int row = id >> 2, ci = id & 3;
        size_t gofs = ((size_t)(m0 + row) * Kdim + k0) * 2 + ci * 16;
        uint32_t so = (uint32_t)(row * 64 + ((ci ^ ((row >> 1) & 3)) << 4));
        cpasync16(sst + so, (const char*)g_colh + gofs);
        cpasync16(sst + 8192 + so, (const char*)g_coll + gofs);
    }
    #pragma unroll
    for (int p = 0; p < 2; p++) {
        int id = tid + p * 256;               // 0..511
        int o = id >> 2, cc = id & 3;
        uint32_t so = (uint32_t)(o * 64 + ((cc ^ ((o >> 1) & 3)) << 4));
        const __half* gh = g_Bh + (size_t)kc * (Pp * 32) + (n0 + o) * 32 + cc * 8;
        cpasync16(sst + 16384 + so, gh);
    }
}

__global__ __launch_bounds__(256, 2) void k_gemm_mma()
{
    extern __shared__ char smem[];
    uint32_t sb = smem_u32(smem);
    int tid = threadIdx.x;
    int lane = tid & 31, wid = tid >> 5;
    int wm = wid & 1, wn = wid >> 1;
    int m0 = blockIdx.x * 128;
    int n0 = blockIdx.y * 128;

    int q = lane >> 3, r = lane & 7;
    int acix = q >> 1;
    uint32_t aoff[4];
    int asw[4];
    #pragma unroll
    for (int fm = 0; fm < 4; fm++) {
        int row = wm * 64 + fm * 16 + (q & 1) * 8 + r;
        aoff[fm] = (uint32_t)(row * 64);
        asw[fm] = (row >> 1) & 3;
    }
    int bno[2], bsw[2];
    int cq = q & 1;
    #pragma unroll
    for (int g = 0; g < 2; g++) {
        int n = wn * 32 + g * 16 + ((q >> 1) & 1) * 8 + r;
        bno[g] = n * 64;
        bsw[g] = (n >> 1) & 3;
    }

    float acc[4][4][4];
    #pragma unroll
    for (int fm = 0; fm < 4; fm++)
        #pragma unroll
        for (int fn = 0; fn < 4; fn++)
            #pragma unroll
            for (int i = 0; i < 4; i++) acc[fm][fn][i] = 0.f;

    issue_tile(0, sb, tid, m0, n0);
    cp_commit();

    for (int it = 0; it < NIT; it++) {
        if (it + 1 < NIT) {
            issue_tile(it + 1, sb + ((it + 1) & 1) * STAGE, tid, m0, n0);
            cp_commit();
            cp_wait<1>();
        } else {
            cp_wait<0>();
        }
        __syncthreads();

        uint32_t abase = sb + (it & 1) * STAGE;
        uint32_t bbase = abase + 16384;

        #pragma unroll
        for (int ks = 0; ks < 2; ks++) {
            uint32_t ah[4][4], al[4][4], bq[2][4];
            #pragma unroll
            for (int fm = 0; fm < 4; fm++) {
                int ci = ks * 2 + acix;
                uint32_t so = aoff[fm] + ((ci ^ asw[fm]) << 4);
                ldsm4(ah[fm], abase + so);
                ldsm4(al[fm], abase + 8192 + so);
            }
            #pragma unroll
            for (int g = 0; g < 2; g++)
                ldsm4(bq[g], bbase + bno[g] + (((ks * 2 + cq) ^ bsw[g]) << 4));
            #pragma unroll
            for (int g = 0; g < 2; g++)
                #pragma unroll
                for (int h = 0; h < 2; h++)
                    #pragma unroll
                    for (int fm = 0; fm < 4; fm++) {
                        mma16816(acc[fm][g * 2 + h], ah[fm], &bq[g][h * 2]);
                        mma16816(acc[fm][g * 2 + h], al[fm], &bq[g][h * 2]);
                    }
        }
        __syncthreads();
    }

    int mrow = m0 + wm * 64 + (lane >> 2);
    int ocol = n0 + wn * 32 + (lane & 3) * 2;
    #pragma unroll
    for (int fm = 0; fm < 4; fm++) {
        int m = mrow + fm * 16;
        #pragma unroll
        for (int fn = 0; fn < 4; fn++) {
            int o = ocol + fn * 8;
            *(float2*)&g_y[(size_t)m * Pp + o]       = make_float2(acc[fm][fn][0], acc[fm][fn][1]);
            *(float2*)&g_y[(size_t)(m + 8) * Pp + o] = make_float2(acc[fm][fn][2], acc[fm][fn][3]);
        }
    }
}

// ---------------- kernel 7: BN partial stats ----------------
__global__ __launch_bounds__(256) void k_bnstats()
{
    int bb = blockIdx.x, t = threadIdx.x;
    float s = 0.f, s2 = 0.f;
    const float* yr = g_y + (size_t)bb * 128 * Pp + t;
    for (int i = 0; i < 128; i++) {
        float v = yr[(size_t)i * Pp];
        s += v;
        s2 = fmaf(v, v, s2);
    }
    g_psum[bb * Pp + t] = s;
    g_psum2[bb * Pp + t] = s2;
}

// ---------------- kernel 8: BN finalize ----------------
__global__ __launch_bounds__(256) void k_bnfin(
    const float* __restrict__ gamma, const float* __restrict__ beta)
{
    int o = threadIdx.x;
    float s = 0.f, s2 = 0.f;
    for (int b = 0; b < 128; b++) {
        s += g_psum[b * Pp + o];
        s2 += g_psum2[b * Pp + o];
    }
    float mean = s * (1.f / (float)Mpix);
    float var = s2 * (1.f / (float)Mpix) - mean * mean;
    float sc = gamma[o] * rsqrtf(var + 1e-5f);
    g_scale[o] = sc;
    g_shift[o] = beta[o] - mean * sc;
}

// ---------------- kernel 9: BN apply + ReLU ----------------
__global__ __launch_bounds__(256) void k_bnapply(float* __restrict__ out)
{
    __shared__ float st[256][36];
    __shared__ float sc[256], sh[256];
    int t = threadIdx.x;
    int m0 = blockIdx.x * 32;
    sc[t] = g_scale[t];
    sh[t] = g_shift[t];
    __syncthreads();

    #pragma unroll
    for (int p = 0; p < 8; p++) {
        int idx = t + p * 256;
        int mi = idx >> 6, oc4 = idx & 63;
        float4 v = *(const float4*)&g_y[(size_t)(m0 + mi) * Pp + oc4 * 4];
        int o = oc4 * 4;
        st[o + 0][mi] = fmaxf(fmaf(v.x, sc[o + 0], sh[o + 0]), 0.f);
        st[o + 1][mi] = fmaxf(fmaf(v.y, sc[o + 1], sh[o + 1]), 0.f);
        st[o + 2][mi] = fmaxf(fmaf(v.z, sc[o + 2], sh[o + 2]), 0.f);
        st[o + 3][mi] = fmaxf(fmaf(v.w, sc[o + 3], sh[o + 3]), 0.f);
    }
    __syncthreads();

    int b = m0 >> 12;
    int hw0 = m0 & 4095;
    #pragma unroll
    for (int p = 0; p < 8; p++) {
        int idx = t + p * 256;
        int o = idx >> 3, mq = idx & 7;
        float4 v = *(const float4*)&st[o][mq * 4];
        *(float4*)&out[(size_t)(b * 256 + o) * 4096 + hw0 + mq * 4] = v;
    }
}

// ---------------- launch ----------------
extern "C" void kernel_launch(void* const* d_in, const int* in_sizes, int n_in,
                              void* d_out, int out_size)
{
    const float* x     = (const float*)d_in[0];
    const float* w_p   = (const float*)d_in[1];
    const float* b_p   = (const float*)d_in[2];
    const float* w_m   = (const float*)d_in[3];
    const float* b_m   = (const float*)d_in[4];
    const float* w     = (const float*)d_in[5];
    const float* gamma = (const float*)d_in[6];
    const float* beta  = (const float*)d_in[7];
    float* out = (float*)d_out;

    cudaFuncSetAttribute(k_gemm_mma, cudaFuncAttributeMaxDynamicSharedMemorySize, GEMM_SMEM);
    cudaFuncSetAttribute(k_convmma, cudaFuncAttributeMaxDynamicSharedMemorySize, CONV_SMEM);

    k_xsplit<<<dim3(128, 8, Bn), dim3(32, 8)>>>(x);
    k_wcpack<<<288, 256>>>(w_p, w_m);
    k_convmma<<<Mpix / 128, 256, CONV_SMEM>>>(b_p, b_m);
    k_sample2<<<Mpix * 9 / 8, 256>>>();
    k_wpack<<<(Pp * Kdim + 255) / 256, 256>>>(w);
    k_gemm_mma<<<dim3(Mpix / 128, 2), 256, GEMM_SMEM>>>();
    k_bnstats<<<128, 256>>>();
    k_bnfin<<<1, 256>>>(gamma, beta);
    k_bnapply<<<Mpix / 32, 256>>>(out);
}